// round 3
// baseline (speedup 1.0000x reference)
#include <cuda_runtime.h>
#include <math.h>
#include <stdint.h>

#define NN 50000
#define DD 128
#define GG 8
#define EPSV 1e-5f

// ---------------- scratch (static device globals; no allocation) ----------------
__device__ float g_agg[(size_t)NN * DD];   // neighbor sum
__device__ float g_f[(size_t)NN * DD];     // post-GELU features
__device__ float g_deg[NN];
__device__ float g_inv[NN];
__device__ float g_sumf[GG * DD];
__device__ float g_sumf2[GG * DD];
__device__ float g_cnt[GG];
__device__ float g_scaleA[GG * DD];
__device__ float g_shiftB[GG * DD];

// ---------------- K0: zero scratch ----------------
__global__ void k_zero() {
    int i = blockIdx.x * blockDim.x + threadIdx.x;
    if (i < NN * 32) ((float4*)g_agg)[i] = make_float4(0.f, 0.f, 0.f, 0.f);
    if (i < NN) g_deg[i] = 0.f;
    if (i < GG * DD) { g_sumf[i] = 0.f; g_sumf2[i] = 0.f; }
    if (i < GG) g_cnt[i] = 0.f;
}

// ---------------- K1: edge scatter (1 warp per edge, vector RED) ----------------
__global__ void k_edges(const float* __restrict__ x, const int* __restrict__ ei, int E) {
    int w = (blockIdx.x * blockDim.x + threadIdx.x) >> 5;
    int lane = threadIdx.x & 31;
    if (w >= E) return;
    int s = __ldg(&ei[w]);
    int d = __ldg(&ei[E + w]);
    float4 v = __ldg(&((const float4*)x)[(size_t)s * 32 + lane]);
    float* a = &g_agg[(size_t)d * DD + lane * 4];
    asm volatile("red.global.add.v4.f32 [%0], {%1,%2,%3,%4};"
                 :: "l"(a), "f"(v.x), "f"(v.y), "f"(v.z), "f"(v.w) : "memory");
    if (lane == 0) atomicAdd(&g_deg[d], 1.0f);
}

// ---------------- K2: inverse degree + per-graph counts ----------------
__global__ void k_prep(const int* __restrict__ batch, int n) {
    __shared__ int hist[GG];
    if (threadIdx.x < GG) hist[threadIdx.x] = 0;
    __syncthreads();
    int i = blockIdx.x * blockDim.x + threadIdx.x;
    if (i < n) {
        g_inv[i] = 1.0f / fmaxf(g_deg[i], 1.0f);
        atomicAdd(&hist[batch[i]], 1);
    }
    __syncthreads();
    if (threadIdx.x < GG && hist[threadIdx.x] > 0)
        atomicAdd(&g_cnt[threadIdx.x], (float)hist[threadIdx.x]);
}

// ---------------- K3: fused GEMM (K=256: [agg/deg | x] @ [Wl | Wr]^T)
//                  + bias + exact GELU + per-graph sum/sum2 ----------------
// Tile: 128 rows x 128 cols, 256 threads, 8x8 register blocking per thread.
// smem staged k-major (transposed), BK=32 chunks, pad to LDT=132 for bank spread.
// Static smem: 2 * 32 * 132 * 4 = 33792 bytes (< 48KB static limit).
#define LDT 132

__global__ __launch_bounds__(256) void k_gemm(
    const float* __restrict__ x, const float* __restrict__ Wl,
    const float* __restrict__ bl, const float* __restrict__ Wr,
    const int* __restrict__ batch, int n)
{
    __shared__ float sA[32 * LDT];
    __shared__ float sW[32 * LDT];

    const int tid = threadIdx.x;
    const int tx = tid & 15;          // col group: cols tx*8 .. tx*8+7
    const int ty = tid >> 4;          // row group: rows ty*8 .. ty*8+7
    const int row0 = blockIdx.x * 128;
    const int kv = tid & 7;           // float4 index within 32-k chunk
    const int rb = tid >> 3;          // 0..31

    float acc[8][8];
#pragma unroll
    for (int i = 0; i < 8; ++i)
#pragma unroll
        for (int j = 0; j < 8; ++j) acc[i][j] = 0.f;

    // K = 256 total: chunks 0..3 from (agg * inv_deg, Wl), chunks 4..7 from (x, Wr)
    for (int kc = 0; kc < 8; ++kc) {
        const bool isA = (kc < 4);
        const int kq = (kc & 3) * 8;  // float4 base index into the 128-wide source
        __syncthreads();
#pragma unroll
        for (int p = 0; p < 4; ++p) {
            int r = rb + p * 32;      // local row / output col 0..127
            int gr = row0 + r;
            float4 v = make_float4(0.f, 0.f, 0.f, 0.f);
            if (gr < n) {
                if (isA) {
                    v = __ldg(&((const float4*)g_agg)[(size_t)gr * 32 + kq + kv]);
                    float iv = g_inv[gr];
                    v.x *= iv; v.y *= iv; v.z *= iv; v.w *= iv;
                } else {
                    v = __ldg(&((const float4*)x)[(size_t)gr * 32 + kq + kv]);
                }
            }
            int kb = kv * 4;
            sA[(kb + 0) * LDT + r] = v.x; sA[(kb + 1) * LDT + r] = v.y;
            sA[(kb + 2) * LDT + r] = v.z; sA[(kb + 3) * LDT + r] = v.w;

            const float4* Wsrc = isA ? (const float4*)Wl : (const float4*)Wr;
            float4 w = __ldg(&Wsrc[(size_t)r * 32 + kq + kv]);
            sW[(kb + 0) * LDT + r] = w.x; sW[(kb + 1) * LDT + r] = w.y;
            sW[(kb + 2) * LDT + r] = w.z; sW[(kb + 3) * LDT + r] = w.w;
        }
        __syncthreads();

#pragma unroll
        for (int k = 0; k < 32; ++k) {
            const float* pa = sA + k * LDT + ty * 8;
            const float* pw = sW + k * LDT + tx * 8;
            float4 A0 = *(const float4*)(pa);     float4 A1 = *(const float4*)(pa + 4);
            float4 W0 = *(const float4*)(pw);     float4 W1 = *(const float4*)(pw + 4);
            float av[8] = {A0.x, A0.y, A0.z, A0.w, A1.x, A1.y, A1.z, A1.w};
            float wv[8] = {W0.x, W0.y, W0.z, W0.w, W1.x, W1.y, W1.z, W1.w};
#pragma unroll
            for (int i = 0; i < 8; ++i)
#pragma unroll
                for (int j = 0; j < 8; ++j)
                    acc[i][j] = fmaf(av[i], wv[j], acc[i][j]);
        }
    }

    // ---- epilogue: bias + exact GELU + store f + per-graph sum/sum2 ----
    float4 b0 = __ldg(&((const float4*)bl)[tx * 2]);
    float4 b1 = __ldg(&((const float4*)bl)[tx * 2 + 1]);
    float bb[8] = {b0.x, b0.y, b0.z, b0.w, b1.x, b1.y, b1.z, b1.w};

    float sf[8], sf2[8];
#pragma unroll
    for (int j = 0; j < 8; ++j) { sf[j] = 0.f; sf2[j] = 0.f; }
    int gprev = -1;

#pragma unroll
    for (int i = 0; i < 8; ++i) {
        int r = row0 + ty * 8 + i;
        if (r < n) {
            int g = batch[r];
            if (g != gprev) {
                if (gprev >= 0) {
#pragma unroll
                    for (int j = 0; j < 8; ++j) {
                        atomicAdd(&g_sumf[gprev * DD + tx * 8 + j], sf[j]);
                        atomicAdd(&g_sumf2[gprev * DD + tx * 8 + j], sf2[j]);
                        sf[j] = 0.f; sf2[j] = 0.f;
                    }
                }
                gprev = g;
            }
            float fv[8];
#pragma unroll
            for (int j = 0; j < 8; ++j) {
                float v = acc[i][j] + bb[j];
                v = 0.5f * v * (1.0f + erff(v * 0.70710678118654752f));
                fv[j] = v;
                sf[j] += v;
                sf2[j] += v * v;
            }
            float4 o0 = make_float4(fv[0], fv[1], fv[2], fv[3]);
            float4 o1 = make_float4(fv[4], fv[5], fv[6], fv[7]);
            ((float4*)g_f)[(size_t)r * 32 + tx * 2] = o0;
            ((float4*)g_f)[(size_t)r * 32 + tx * 2 + 1] = o1;
        }
    }
    if (gprev >= 0) {
#pragma unroll
        for (int j = 0; j < 8; ++j) {
            atomicAdd(&g_sumf[gprev * DD + tx * 8 + j], sf[j]);
            atomicAdd(&g_sumf2[gprev * DD + tx * 8 + j], sf2[j]);
        }
    }
}

// ---------------- K4: fold stats into per-(graph,col) scale/shift ----------------
__global__ void k_norm(const float* __restrict__ gw, const float* __restrict__ gb,
                       const float* __restrict__ ms) {
    int i = threadIdx.x;              // 1024 = G*D
    int c = i & 127;
    int g = i >> 7;
    float cnt = fmaxf(g_cnt[g], 1.0f);
    float m = g_sumf[i] / cnt;
    float e2 = g_sumf2[i] / cnt;
    float s = ms[c];
    float var = e2 - (2.0f * s - s * s) * m * m;   // E[(f - s*m)^2]
    var = fmaxf(var, 0.0f);
    float inv = rsqrtf(var + EPSV);
    float w = gw[c];
    g_scaleA[i] = inv * w;
    g_shiftB[i] = gb[c] - s * m * inv * w;
}

// ---------------- K5: out = f*scaleA + shiftB + x ----------------
__global__ void k_out(const float* __restrict__ x, const int* __restrict__ batch,
                      float* __restrict__ out, int n) {
    int i = blockIdx.x * blockDim.x + threadIdx.x;
    if (i >= n * 32) return;
    int row = i >> 5;
    int c4 = i & 31;
    int g = batch[row];                       // uniform per warp (1 warp == 1 row)
    float4 f = ((const float4*)g_f)[i];
    float4 s = __ldg(&((const float4*)g_scaleA)[g * 32 + c4]);
    float4 b = __ldg(&((const float4*)g_shiftB)[g * 32 + c4]);
    float4 xv = ((const float4*)x)[i];
    float4 o;
    o.x = fmaf(f.x, s.x, b.x) + xv.x;
    o.y = fmaf(f.y, s.y, b.y) + xv.y;
    o.z = fmaf(f.z, s.z, b.z) + xv.z;
    o.w = fmaf(f.w, s.w, b.w) + xv.w;
    ((float4*)out)[i] = o;
}

// ---------------- host launcher ----------------
extern "C" void kernel_launch(void* const* d_in, const int* in_sizes, int n_in,
                              void* d_out, int out_size) {
    const float* x     = (const float*)d_in[0];
    const int*   ei    = (const int*)d_in[1];
    const int*   batch = (const int*)d_in[2];
    // d_in[3] = num_graphs (fixed G=8)
    const float* Wl = (const float*)d_in[4];
    const float* bl = (const float*)d_in[5];
    const float* Wr = (const float*)d_in[6];
    const float* gw = (const float*)d_in[7];
    const float* gb = (const float*)d_in[8];
    const float* ms = (const float*)d_in[9];

    int n = in_sizes[0] / DD;
    int E = in_sizes[1] / 2;

    k_zero<<<(NN * 32 + 255) / 256, 256>>>();
    k_edges<<<((size_t)E * 32 + 255) / 256, 256>>>(x, ei, E);
    k_prep<<<(n + 255) / 256, 256>>>(batch, n);
    k_gemm<<<(n + 127) / 128, 256>>>(x, Wl, bl, Wr, batch, n);
    k_norm<<<1, 1024>>>(gw, gb, ms);
    k_out<<<(n * 32 + 255) / 256, 256>>>(x, batch, (float*)d_out, n);
}